// round 1
// baseline (speedup 1.0000x reference)
#include <cuda_runtime.h>

#define UNITS 224
#define SENS  64
#define MOTORN 32
#define OUTL  32
#define NB    32
#define NT    32
#define UNF   6
#define CAP   64
#define SCAP  32
#define NTHREADS 448
#define LOG2E 1.4426950408889634f

// Compacted synapse tables (built by prep kernel each launch; deterministic).
__device__ float4 g_syn [CAP  * UNITS];  // {a=sig*log2e, b=sig*mu*log2e, wm, wme}
__device__ int    g_idx [CAP  * UNITS];
__device__ int    g_cnt [UNITS];         // -1 => overflow -> dense fallback
__device__ float4 g_ssyn[SCAP * UNITS];
__device__ int    g_sidx[SCAP * UNITS];
__device__ int    g_scnt[UNITS];

__device__ __forceinline__ float ex2f(float x) {
    float r; asm("ex2.approx.ftz.f32 %0, %1;" : "=f"(r) : "f"(x)); return r;
}
__device__ __forceinline__ float rcpf(float x) {
    float r; asm("rcp.approx.ftz.f32 %0, %1;" : "=f"(r) : "f"(x)); return r;
}

__global__ void prep_kernel(
    const float* __restrict__ smu,  const float* __restrict__ ssig,
    const float* __restrict__ swt,  const float* __restrict__ serev,
    const float* __restrict__ smask,
    const float* __restrict__ mu,   const float* __restrict__ sig,
    const float* __restrict__ wt,   const float* __restrict__ erev,
    const float* __restrict__ mask)
{
    int j = threadIdx.x;
    if (j >= UNITS) return;

    // ---- recurrent synapses, column j ----
    int cnt = 0;
    for (int i0 = 0; i0 < UNITS; i0 += 8) {
        float mv[8], sg[8], uu[8], ww[8], ev[8];
#pragma unroll
        for (int r = 0; r < 8; r++) {
            int idx = (i0 + r) * UNITS + j;
            mv[r] = mask[idx]; sg[r] = sig[idx]; uu[r] = mu[idx];
            ww[r] = wt[idx];   ev[r] = erev[idx];
        }
#pragma unroll
        for (int r = 0; r < 8; r++) {
            if (mv[r] != 0.f) {
                if (cnt < CAP) {
                    float wm = ww[r] * mv[r];
                    g_syn[cnt * UNITS + j] =
                        make_float4(sg[r] * LOG2E, sg[r] * uu[r] * LOG2E, wm, wm * ev[r]);
                    g_idx[cnt * UNITS + j] = i0 + r;
                }
                cnt++;
            }
        }
    }
    g_cnt[j] = (cnt <= CAP) ? cnt : -1;

    // ---- sensory synapses, column j ----
    cnt = 0;
    for (int i0 = 0; i0 < SENS; i0 += 8) {
        float mv[8], sg[8], uu[8], ww[8], ev[8];
#pragma unroll
        for (int r = 0; r < 8; r++) {
            int idx = (i0 + r) * UNITS + j;
            mv[r] = smask[idx]; sg[r] = ssig[idx]; uu[r] = smu[idx];
            ww[r] = swt[idx];   ev[r] = serev[idx];
        }
#pragma unroll
        for (int r = 0; r < 8; r++) {
            if (mv[r] != 0.f) {
                if (cnt < SCAP) {
                    float wm = ww[r] * mv[r];
                    g_ssyn[cnt * UNITS + j] =
                        make_float4(sg[r] * LOG2E, sg[r] * uu[r] * LOG2E, wm, wm * ev[r]);
                    g_sidx[cnt * UNITS + j] = i0 + r;
                }
                cnt++;
            }
        }
    }
    g_scnt[j] = (cnt <= SCAP) ? cnt : -1;
}

__global__ void __launch_bounds__(NTHREADS)
ncp_kernel(
    const float* __restrict__ inputs,
    const float* __restrict__ input_w, const float* __restrict__ input_b,
    const float* __restrict__ smu,  const float* __restrict__ ssig,
    const float* __restrict__ swt,  const float* __restrict__ serev,
    const float* __restrict__ smask,
    const float* __restrict__ mu,   const float* __restrict__ sig,
    const float* __restrict__ wt,   const float* __restrict__ erev,
    const float* __restrict__ mask,
    const float* __restrict__ gleak, const float* __restrict__ vleak,
    const float* __restrict__ cm,
    const float* __restrict__ output_w, const float* __restrict__ output_b,
    const float* __restrict__ dense_w,  const float* __restrict__ dense_b,
    float* __restrict__ out)
{
    __shared__ float sv[UNITS];
    __shared__ float sx[SENS];
    __shared__ float siw[SENS], sib[SENS];
    __shared__ float sow[MOTORN], sob[MOTORN], sdb[OUTL];
    __shared__ float sdw[MOTORN * OUTL];

    const int t = threadIdx.x;
    const int b = blockIdx.x;
    const int j = t >> 1;   // post neuron
    const int h = t & 1;    // half (2 threads per post)

    if (t < UNITS) sv[t] = 0.f;
    if (t < SENS)  { siw[t] = input_w[t]; sib[t] = input_b[t]; }
    if (t < MOTORN) { sow[t] = output_w[t]; sob[t] = output_b[t]; }
    if (t < OUTL)  sdb[t] = dense_b[t];
    for (int i = t; i < MOTORN * OUTL; i += NTHREADS) sdw[i] = dense_w[i];

    const float cmt = cm[j] * (float)UNF;
    const float gl  = gleak[j];
    const float gv  = gl * vleak[j];
    const int   c   = g_cnt[j];
    const int   scnt = g_scnt[j];
    __syncthreads();

    for (int step = 0; step < NT; step++) {
        if (t < SENS)
            sx[t] = inputs[(b * NT + step) * SENS + t] * siw[t] + sib[t];
        __syncthreads();

        // sensory sums (per-half partials; full sum formed by the shfl below)
        float sn = 0.f, sd = 0.f;
        if (scnt >= 0) {
#pragma unroll 4
            for (int k = h; k < scnt; k += 2) {
                int base = k * UNITS + j;
                float4 sy = g_ssyn[base];
                float x = sx[g_sidx[base]];
                float e = ex2f(fmaf(-sy.x, x, sy.y));   // exp(-sig*(x-mu))
                float s = rcpf(1.f + e);
                sd = fmaf(sy.z, s, sd);
                sn = fmaf(sy.w, s, sn);
            }
        } else {  // dense fallback (correctness insurance for pathological masks)
            for (int i = h; i < SENS; i += 2) {
                float m = smask[i * UNITS + j];
                if (m != 0.f) {
                    float sg = ssig[i * UNITS + j];
                    float e = ex2f(LOG2E * (sg * smu[i * UNITS + j] - sg * sx[i]));
                    float s = rcpf(1.f + e);
                    float wm = swt[i * UNITS + j] * m;
                    sd += wm * s;
                    sn += wm * serev[i * UNITS + j] * s;
                }
            }
        }

        for (int u = 0; u < UNF; u++) {
            float na = sn, da = sd;
            if (c >= 0) {
#pragma unroll 4
                for (int k = h; k < c; k += 2) {
                    int base = k * UNITS + j;
                    float4 sy = g_syn[base];
                    float vp = sv[g_idx[base]];
                    float e = ex2f(fmaf(-sy.x, vp, sy.y));
                    float s = rcpf(1.f + e);
                    da = fmaf(sy.z, s, da);
                    na = fmaf(sy.w, s, na);
                }
            } else {  // dense fallback
                for (int i = h; i < UNITS; i += 2) {
                    float m = mask[i * UNITS + j];
                    if (m != 0.f) {
                        float sg = sig[i * UNITS + j];
                        float e = ex2f(LOG2E * (sg * mu[i * UNITS + j] - sg * sv[i]));
                        float s = rcpf(1.f + e);
                        float wm = wt[i * UNITS + j] * m;
                        da += wm * s;
                        na += wm * erev[i * UNITS + j] * s;
                    }
                }
            }
            na += __shfl_xor_sync(0xffffffffu, na, 1);
            da += __shfl_xor_sync(0xffffffffu, da, 1);
            float vn = 0.f;
            if (h == 0) {
                float vj = sv[j];
                vn = (cmt * vj + gv + na) * rcpf(cmt + gl + da + 1e-8f);
            }
            __syncthreads();
            if (h == 0) sv[j] = vn;
            __syncthreads();
        }

        // output projection: out[b, step, o] = sum_m (v_m*ow_m + ob_m) * dw[m,o] + db_o
        if (t < OUTL) {
            float acc = sdb[t];
#pragma unroll
            for (int m = 0; m < MOTORN; m++)
                acc = fmaf(fmaf(sv[m], sow[m], sob[m]), sdw[m * OUTL + t], acc);
            out[(b * NT + step) * OUTL + t] = acc;
        }
    }
}

extern "C" void kernel_launch(void* const* d_in, const int* in_sizes, int n_in,
                              void* d_out, int out_size)
{
    const float* inputs   = (const float*)d_in[0];
    const float* input_w  = (const float*)d_in[1];
    const float* input_b  = (const float*)d_in[2];
    const float* smu      = (const float*)d_in[3];
    const float* ssig     = (const float*)d_in[4];
    const float* swt      = (const float*)d_in[5];
    const float* serev    = (const float*)d_in[6];
    const float* smask    = (const float*)d_in[7];
    const float* mu       = (const float*)d_in[8];
    const float* sig      = (const float*)d_in[9];
    const float* wt       = (const float*)d_in[10];
    const float* erev     = (const float*)d_in[11];
    const float* mask     = (const float*)d_in[12];
    const float* gleak    = (const float*)d_in[13];
    const float* vleak    = (const float*)d_in[14];
    const float* cm       = (const float*)d_in[15];
    const float* output_w = (const float*)d_in[16];
    const float* output_b = (const float*)d_in[17];
    const float* dense_w  = (const float*)d_in[18];
    const float* dense_b  = (const float*)d_in[19];
    float* out = (float*)d_out;

    prep_kernel<<<1, 256>>>(smu, ssig, swt, serev, smask, mu, sig, wt, erev, mask);
    ncp_kernel<<<NB, NTHREADS>>>(inputs, input_w, input_b,
                                 smu, ssig, swt, serev, smask,
                                 mu, sig, wt, erev, mask,
                                 gleak, vleak, cm,
                                 output_w, output_b, dense_w, dense_b, out);
}

// round 2
// speedup vs baseline: 1.6007x; 1.6007x over previous
#include <cuda_runtime.h>

#define UNITS 224
#define SENS  64
#define MOTORN 32
#define OUTL  32
#define NB    32
#define NT    32
#define UNF   6
#define CAP   128
#define SCAP  64
#define NTHREADS 448
#define LOG2E 1.4426950408889634f

// Compacted synapse tables, padded per-post layout [post][CAP] (L1-resident
// hot footprint ~75KB vs 246KB for the old strided layout).
__device__ float4 g_syn [UNITS * CAP];   // {a=sig*log2e, b=sig*mu*log2e, wm, wm*erev}
__device__ int    g_idx [UNITS * CAP];
__device__ int    g_cnt [UNITS];         // -1 => overflow -> dense fallback
__device__ float4 g_ssyn[UNITS * SCAP];
__device__ int    g_sidx[UNITS * SCAP];
__device__ int    g_scnt[UNITS];

__device__ __forceinline__ float ex2f(float x) {
    float r; asm("ex2.approx.ftz.f32 %0, %1;" : "=f"(r) : "f"(x)); return r;
}
__device__ __forceinline__ float rcpf(float x) {
    float r; asm("rcp.approx.ftz.f32 %0, %1;" : "=f"(r) : "f"(x)); return r;
}

// One block (1 warp) per post column; ballot-based stream compaction.
__global__ void prep_kernel(
    const float* __restrict__ smu,  const float* __restrict__ ssig,
    const float* __restrict__ swt,  const float* __restrict__ serev,
    const float* __restrict__ smask,
    const float* __restrict__ mu,   const float* __restrict__ sig,
    const float* __restrict__ wt,   const float* __restrict__ erev,
    const float* __restrict__ mask)
{
    const int j    = blockIdx.x;
    const int lane = threadIdx.x;
    const unsigned FULL = 0xffffffffu;

    // ---- recurrent synapses, column j (224 rows = 7 chunks of 32) ----
    int cnt = 0;
    for (int i0 = 0; i0 < UNITS; i0 += 32) {
        const int i = i0 + lane;
        const int gi = i * UNITS + j;
        float m = mask[gi];
        unsigned bal = __ballot_sync(FULL, m != 0.f);
        if (m != 0.f) {
            int pos = cnt + __popc(bal & ((1u << lane) - 1u));
            if (pos < CAP) {
                float sg = sig[gi];
                float wm = wt[gi] * m;
                g_syn[j * CAP + pos] =
                    make_float4(sg * LOG2E, sg * mu[gi] * LOG2E, wm, wm * erev[gi]);
                g_idx[j * CAP + pos] = i;
            }
        }
        cnt += __popc(bal);
    }
    if (lane == 0) g_cnt[j] = (cnt <= CAP) ? cnt : -1;

    // ---- sensory synapses, column j (64 rows = 2 chunks of 32) ----
    cnt = 0;
    for (int i0 = 0; i0 < SENS; i0 += 32) {
        const int i = i0 + lane;
        const int gi = i * UNITS + j;
        float m = smask[gi];
        unsigned bal = __ballot_sync(FULL, m != 0.f);
        if (m != 0.f) {
            int pos = cnt + __popc(bal & ((1u << lane) - 1u));
            if (pos < SCAP) {
                float sg = ssig[gi];
                float wm = swt[gi] * m;
                g_ssyn[j * SCAP + pos] =
                    make_float4(sg * LOG2E, sg * smu[gi] * LOG2E, wm, wm * serev[gi]);
                g_sidx[j * SCAP + pos] = i;
            }
        }
        cnt += __popc(bal);
    }
    if (lane == 0) g_scnt[j] = (cnt <= SCAP) ? cnt : -1;
}

__global__ void __launch_bounds__(NTHREADS)
ncp_kernel(
    const float* __restrict__ inputs,
    const float* __restrict__ input_w, const float* __restrict__ input_b,
    const float* __restrict__ smu,  const float* __restrict__ ssig,
    const float* __restrict__ swt,  const float* __restrict__ serev,
    const float* __restrict__ smask,
    const float* __restrict__ mu,   const float* __restrict__ sig,
    const float* __restrict__ wt,   const float* __restrict__ erev,
    const float* __restrict__ mask,
    const float* __restrict__ gleak, const float* __restrict__ vleak,
    const float* __restrict__ cm,
    const float* __restrict__ output_w, const float* __restrict__ output_b,
    const float* __restrict__ dense_w,  const float* __restrict__ dense_b,
    float* __restrict__ out)
{
    __shared__ float sva[UNITS];
    __shared__ float svb[UNITS];
    __shared__ float sx[SENS];
    __shared__ float sow[MOTORN], sob[MOTORN], sdb[OUTL];
    __shared__ float sdw[MOTORN * OUTL];

    const int t = threadIdx.x;
    const int b = blockIdx.x;
    const int j = t >> 1;   // post neuron (448/2 = 224 = UNITS)
    const int h = t & 1;    // half (2 threads per post)

    if (t < UNITS) { sva[t] = 0.f; }
    if (t < MOTORN) { sow[t] = output_w[t]; sob[t] = output_b[t]; }
    if (t < OUTL)  sdb[t] = dense_b[t];
    for (int i = t; i < MOTORN * OUTL; i += NTHREADS) sdw[i] = dense_w[i];

    const float cmt  = cm[j] * (float)UNF;
    const float gl   = gleak[j];
    const float gv   = gl * vleak[j];
    const int   c    = g_cnt[j];
    const int   scnt = g_scnt[j];
    const float iw   = (t < SENS) ? input_w[t] : 0.f;
    const float ib   = (t < SENS) ? input_b[t] : 0.f;
    __syncthreads();

    float* cur = sva;
    float* nxt = svb;

    for (int step = 0; step < NT; step++) {
        if (t < SENS)
            sx[t] = fmaf(inputs[(b * NT + step) * SENS + t], iw, ib);
        __syncthreads();

        // ---- sensory sums (per-half partials, pair-reduced by shfl) ----
        float sn = 0.f, sd = 0.f;
        if (scnt >= 0) {
#pragma unroll 4
            for (int k = h; k < scnt; k += 2) {
                const int base = j * SCAP + k;
                float4 sy = g_ssyn[base];
                float x = sx[g_sidx[base]];
                float e = ex2f(fmaf(-sy.x, x, sy.y));   // exp(-sig*(x-mu))
                float s = rcpf(1.f + e);
                sd = fmaf(sy.z, s, sd);
                sn = fmaf(sy.w, s, sn);
            }
        } else {  // dense fallback (pathological masks)
            for (int i = h; i < SENS; i += 2) {
                float m = smask[i * UNITS + j];
                if (m != 0.f) {
                    float sg = ssig[i * UNITS + j];
                    float e = ex2f(LOG2E * (sg * smu[i * UNITS + j] - sg * sx[i]));
                    float s = rcpf(1.f + e);
                    float wm = swt[i * UNITS + j] * m;
                    sd += wm * s;
                    sn += wm * serev[i * UNITS + j] * s;
                }
            }
        }
        sn += __shfl_xor_sync(0xffffffffu, sn, 1);
        sd += __shfl_xor_sync(0xffffffffu, sd, 1);
        const float nbase = sn + gv;
        const float dbase = sd + cmt + gl + 1e-8f;

        // ---- ODE unfolds: 1 barrier each (double-buffered v) ----
#pragma unroll
        for (int u = 0; u < UNF; u++) {
            float na = 0.f, da = 0.f;
            if (c >= 0) {
#pragma unroll 4
                for (int k = h; k < c; k += 2) {
                    const int base = j * CAP + k;
                    float4 sy = g_syn[base];
                    float vp = cur[g_idx[base]];
                    float e = ex2f(fmaf(-sy.x, vp, sy.y));
                    float s = rcpf(1.f + e);
                    da = fmaf(sy.z, s, da);
                    na = fmaf(sy.w, s, na);
                }
            } else {  // dense fallback
                for (int i = h; i < UNITS; i += 2) {
                    float m = mask[i * UNITS + j];
                    if (m != 0.f) {
                        float sg = sig[i * UNITS + j];
                        float e = ex2f(LOG2E * (sg * mu[i * UNITS + j] - sg * cur[i]));
                        float s = rcpf(1.f + e);
                        float wm = wt[i * UNITS + j] * m;
                        da += wm * s;
                        na += wm * erev[i * UNITS + j] * s;
                    }
                }
            }
            na += __shfl_xor_sync(0xffffffffu, na, 1);
            da += __shfl_xor_sync(0xffffffffu, da, 1);
            if (h == 0)
                nxt[j] = fmaf(cmt, cur[j], na + nbase) * rcpf(da + dbase);
            __syncthreads();
            float* tmp = cur; cur = nxt; nxt = tmp;
        }

        // ---- output: out[b,step,o] = sum_m (v_m*ow_m+ob_m)*dw[m,o] + db_o ----
        if (t < OUTL) {
            float acc = sdb[t];
#pragma unroll
            for (int m = 0; m < MOTORN; m++)
                acc = fmaf(fmaf(cur[m], sow[m], sob[m]), sdw[m * OUTL + t], acc);
            out[(b * NT + step) * OUTL + t] = acc;
        }
    }
}

extern "C" void kernel_launch(void* const* d_in, const int* in_sizes, int n_in,
                              void* d_out, int out_size)
{
    const float* inputs   = (const float*)d_in[0];
    const float* input_w  = (const float*)d_in[1];
    const float* input_b  = (const float*)d_in[2];
    const float* smu      = (const float*)d_in[3];
    const float* ssig     = (const float*)d_in[4];
    const float* swt      = (const float*)d_in[5];
    const float* serev    = (const float*)d_in[6];
    const float* smask    = (const float*)d_in[7];
    const float* mu       = (const float*)d_in[8];
    const float* sig      = (const float*)d_in[9];
    const float* wt       = (const float*)d_in[10];
    const float* erev     = (const float*)d_in[11];
    const float* mask     = (const float*)d_in[12];
    const float* gleak    = (const float*)d_in[13];
    const float* vleak    = (const float*)d_in[14];
    const float* cm       = (const float*)d_in[15];
    const float* output_w = (const float*)d_in[16];
    const float* output_b = (const float*)d_in[17];
    const float* dense_w  = (const float*)d_in[18];
    const float* dense_b  = (const float*)d_in[19];
    float* out = (float*)d_out;

    prep_kernel<<<UNITS, 32>>>(smu, ssig, swt, serev, smask, mu, sig, wt, erev, mask);
    ncp_kernel<<<NB, NTHREADS>>>(inputs, input_w, input_b,
                                 smu, ssig, swt, serev, smask,
                                 mu, sig, wt, erev, mask,
                                 gleak, vleak, cm,
                                 output_w, output_b, dense_w, dense_b, out);
}